// round 1
// baseline (speedup 1.0000x reference)
#include <cuda_runtime.h>

#define CH   1024
#define NB   8
#define SEQ  2048
#define MTOT (NB*SEQ)      // 16384
#define ODIM 768

// ---------------- scratch (device globals: allocation-guard safe) ----------
__device__ float g_imgn [(size_t)MTOT*CH];
__device__ float g_refn [(size_t)MTOT*CH];
__device__ float g_posen[(size_t)MTOT*CH];
__device__ float g_resid[(size_t)MTOT*CH];
__device__ float g_Q    [(size_t)MTOT*CH];
__device__ float g_K    [(size_t)MTOT*CH];
__device__ float g_V    [(size_t)MTOT*CH];
__device__ float g_S    [(size_t)NB*SEQ*SEQ];   // attention scores, 134 MB
__device__ float g_O    [(size_t)MTOT*CH];

// ---------------- block reductions -----------------------------------------
__device__ __forceinline__ float2 blk_sum2(float a, float b, float2* sm) {
    int lane = threadIdx.x & 31, w = threadIdx.x >> 5;
#pragma unroll
    for (int o = 16; o; o >>= 1) {
        a += __shfl_xor_sync(0xffffffffu, a, o);
        b += __shfl_xor_sync(0xffffffffu, b, o);
    }
    if (lane == 0) sm[w] = make_float2(a, b);
    __syncthreads();
    float sa = 0.f, sb = 0.f;
#pragma unroll
    for (int i = 0; i < 8; i++) { sa += sm[i].x; sb += sm[i].y; }
    __syncthreads();
    return make_float2(sa, sb);
}

__device__ __forceinline__ float blk_max(float a, float* sm) {
    int lane = threadIdx.x & 31, w = threadIdx.x >> 5;
#pragma unroll
    for (int o = 16; o; o >>= 1) a = fmaxf(a, __shfl_xor_sync(0xffffffffu, a, o));
    if (lane == 0) sm[w] = a;
    __syncthreads();
    float m = sm[0];
#pragma unroll
    for (int i = 1; i < 8; i++) m = fmaxf(m, sm[i]);
    __syncthreads();
    return m;
}

__device__ __forceinline__ float blk_sum(float a, float* sm) {
    int lane = threadIdx.x & 31, w = threadIdx.x >> 5;
#pragma unroll
    for (int o = 16; o; o >>= 1) a += __shfl_xor_sync(0xffffffffu, a, o);
    if (lane == 0) sm[w] = a;
    __syncthreads();
    float s = 0.f;
#pragma unroll
    for (int i = 0; i < 8; i++) s += sm[i];
    __syncthreads();
    return s;
}

// ---------------- fused triple LayerNorm + residual precompute --------------
// one block per row; 256 threads * float4 = 1024 elements
__global__ void ln3_kernel(const float* __restrict__ img,  const float* __restrict__ refp,
                           const float* __restrict__ pose,
                           const float* __restrict__ gamma, const float* __restrict__ beta,
                           float* __restrict__ img_n, float* __restrict__ ref_n,
                           float* __restrict__ pose_n, float* __restrict__ resid) {
    __shared__ float2 sm[8];
    long long row  = blockIdx.x;
    int       t    = threadIdx.x;
    long long base = row * CH + (long long)t * 4;

    float4 g  = *(const float4*)(gamma + t*4);
    float4 be = *(const float4*)(beta  + t*4);
    float4 keep_img = make_float4(0.f, 0.f, 0.f, 0.f);

    const float* srcs[3] = {img, refp, pose};
    float*       dsts[3] = {img_n, ref_n, pose_n};

#pragma unroll
    for (int s = 0; s < 3; s++) {
        float4 x = *(const float4*)(srcs[s] + base);
        float su = x.x + x.y + x.z + x.w;
        float sq = x.x*x.x + x.y*x.y + x.z*x.z + x.w*x.w;
        float2 r = blk_sum2(su, sq, sm);
        float mean = r.x * (1.0f/CH);
        float var  = r.y * (1.0f/CH) - mean*mean;
        float rstd = rsqrtf(var + 1e-5f);
        float4 y;
        y.x = (x.x-mean)*rstd*g.x + be.x;
        y.y = (x.y-mean)*rstd*g.y + be.y;
        y.z = (x.z-mean)*rstd*g.z + be.z;
        y.w = (x.w-mean)*rstd*g.w + be.w;
        *(float4*)(dsts[s] + base) = y;
        if (s == 0) keep_img = y;
        if (s == 2) {
            float4 rr = make_float4(keep_img.x + y.x, keep_img.y + y.y,
                                    keep_img.z + y.z, keep_img.w + y.w);
            *(float4*)(resid + base) = rr;
        }
    }
}

// ---------------- NT GEMM: C[M,N] = alpha * A[M,K] @ W[N,K]^T (+bias) -------
// 128x128 block tile, BK=8, 256 threads, 8x8 per-thread, smem double buffer.
// All dims must be multiples of the tile (true for this problem).
__global__ __launch_bounds__(256, 2)
void gemm_nt(const float* __restrict__ A, const float* __restrict__ W,
             const float* __restrict__ bias, float* __restrict__ C,
             int M, int N, int K, float alpha,
             long long sA, long long sB, long long sC) {
    A += (long long)blockIdx.z * sA;
    W += (long long)blockIdx.z * sB;
    C += (long long)blockIdx.z * sC;

    __shared__ float As[2][8][128];
    __shared__ float Bs[2][8][128];

    const int tid  = threadIdx.x;
    const int tx   = tid & 15, ty = tid >> 4;
    const int rowA = blockIdx.y * 128;
    const int colB = blockIdx.x * 128;
    const int ldr  = tid >> 1;           // 0..127
    const int ldc  = (tid & 1) * 4;      // 0 or 4

    const float* pa = A + (long long)(rowA + ldr) * K + ldc;
    const float* pb = W + (long long)(colB + ldr) * K + ldc;

    float4 av = *(const float4*)pa;
    float4 bv = *(const float4*)pb;
    As[0][ldc+0][ldr]=av.x; As[0][ldc+1][ldr]=av.y; As[0][ldc+2][ldr]=av.z; As[0][ldc+3][ldr]=av.w;
    Bs[0][ldc+0][ldr]=bv.x; Bs[0][ldc+1][ldr]=bv.y; Bs[0][ldc+2][ldr]=bv.z; Bs[0][ldc+3][ldr]=bv.w;
    __syncthreads();

    float acc[8][8];
#pragma unroll
    for (int i = 0; i < 8; i++)
#pragma unroll
        for (int j = 0; j < 8; j++) acc[i][j] = 0.f;

    const int nk = K >> 3;
    int buf = 0;
#pragma unroll 1
    for (int kt = 0; kt < nk; ++kt) {
        if (kt + 1 < nk) {
            av = *(const float4*)(pa + (kt+1)*8);
            bv = *(const float4*)(pb + (kt+1)*8);
        }
#pragma unroll
        for (int k = 0; k < 8; ++k) {
            float a[8], b[8];
            *(float4*)(a)   = *(const float4*)&As[buf][k][ty*8];
            *(float4*)(a+4) = *(const float4*)&As[buf][k][ty*8+4];
            *(float4*)(b)   = *(const float4*)&Bs[buf][k][tx*8];
            *(float4*)(b+4) = *(const float4*)&Bs[buf][k][tx*8+4];
#pragma unroll
            for (int i = 0; i < 8; i++)
#pragma unroll
                for (int j = 0; j < 8; j++)
                    acc[i][j] = fmaf(a[i], b[j], acc[i][j]);
        }
        if (kt + 1 < nk) {
            int nb = buf ^ 1;
            As[nb][ldc+0][ldr]=av.x; As[nb][ldc+1][ldr]=av.y; As[nb][ldc+2][ldr]=av.z; As[nb][ldc+3][ldr]=av.w;
            Bs[nb][ldc+0][ldr]=bv.x; Bs[nb][ldc+1][ldr]=bv.y; Bs[nb][ldc+2][ldr]=bv.z; Bs[nb][ldc+3][ldr]=bv.w;
            __syncthreads();
            buf = nb;
        }
    }

    float4 bias0 = make_float4(0.f,0.f,0.f,0.f), bias1 = bias0;
    if (bias) {
        bias0 = *(const float4*)(bias + colB + tx*8);
        bias1 = *(const float4*)(bias + colB + tx*8 + 4);
    }
#pragma unroll
    for (int i = 0; i < 8; i++) {
        long long r = rowA + ty*8 + i;
        float* cp = C + r * (long long)N + colB + tx*8;
        float4 o0 = make_float4(acc[i][0]*alpha + bias0.x, acc[i][1]*alpha + bias0.y,
                                acc[i][2]*alpha + bias0.z, acc[i][3]*alpha + bias0.w);
        float4 o1 = make_float4(acc[i][4]*alpha + bias1.x, acc[i][5]*alpha + bias1.y,
                                acc[i][6]*alpha + bias1.z, acc[i][7]*alpha + bias1.w);
        *(float4*)(cp)     = o0;
        *(float4*)(cp + 4) = o1;
    }
}

// ---------------- NN GEMM: C[M,N] = A[M,K] @ B[K,N] + addend ----------------
__global__ __launch_bounds__(256, 2)
void gemm_nn(const float* __restrict__ A, const float* __restrict__ Bm,
             const float* __restrict__ addend, float* __restrict__ C,
             int M, int N, int K,
             long long sA, long long sB, long long sC, long long sAdd) {
    A      += (long long)blockIdx.z * sA;
    Bm     += (long long)blockIdx.z * sB;
    C      += (long long)blockIdx.z * sC;
    addend += (long long)blockIdx.z * sAdd;

    __shared__ float As[2][8][128];
    __shared__ float Bs[2][8][128];

    const int tid  = threadIdx.x;
    const int tx   = tid & 15, ty = tid >> 4;
    const int rowA = blockIdx.y * 128;
    const int colB = blockIdx.x * 128;
    const int ldr  = tid >> 1;            // A tile: 0..127
    const int ldc  = (tid & 1) * 4;
    const int ldr2 = tid >> 5;            // B tile row: 0..7
    const int ldc2 = (tid & 31) * 4;      // B tile col: 0..124

    const float* pa = A + (long long)(rowA + ldr) * K + ldc;

    float4 av = *(const float4*)pa;
    float4 bv = *(const float4*)(Bm + (long long)ldr2 * N + colB + ldc2);
    As[0][ldc+0][ldr]=av.x; As[0][ldc+1][ldr]=av.y; As[0][ldc+2][ldr]=av.z; As[0][ldc+3][ldr]=av.w;
    *(float4*)&Bs[0][ldr2][ldc2] = bv;
    __syncthreads();

    float acc[8][8];
#pragma unroll
    for (int i = 0; i < 8; i++)
#pragma unroll
        for (int j = 0; j < 8; j++) acc[i][j] = 0.f;

    const int nk = K >> 3;
    int buf = 0;
#pragma unroll 1
    for (int kt = 0; kt < nk; ++kt) {
        if (kt + 1 < nk) {
            av = *(const float4*)(pa + (kt+1)*8);
            bv = *(const float4*)(Bm + (long long)((kt+1)*8 + ldr2) * N + colB + ldc2);
        }
#pragma unroll
        for (int k = 0; k < 8; ++k) {
            float a[8], b[8];
            *(float4*)(a)   = *(const float4*)&As[buf][k][ty*8];
            *(float4*)(a+4) = *(const float4*)&As[buf][k][ty*8+4];
            *(float4*)(b)   = *(const float4*)&Bs[buf][k][tx*8];
            *(float4*)(b+4) = *(const float4*)&Bs[buf][k][tx*8+4];
#pragma unroll
            for (int i = 0; i < 8; i++)
#pragma unroll
                for (int j = 0; j < 8; j++)
                    acc[i][j] = fmaf(a[i], b[j], acc[i][j]);
        }
        if (kt + 1 < nk) {
            int nb = buf ^ 1;
            As[nb][ldc+0][ldr]=av.x; As[nb][ldc+1][ldr]=av.y; As[nb][ldc+2][ldr]=av.z; As[nb][ldc+3][ldr]=av.w;
            *(float4*)&Bs[nb][ldr2][ldc2] = bv;
            __syncthreads();
            buf = nb;
        }
    }

#pragma unroll
    for (int i = 0; i < 8; i++) {
        long long r = rowA + ty*8 + i;
        const float* ap = addend + r * (long long)N + colB + tx*8;
        float*       cp = C      + r * (long long)N + colB + tx*8;
        float4 r0 = *(const float4*)(ap);
        float4 r1 = *(const float4*)(ap + 4);
        float4 o0 = make_float4(acc[i][0]+r0.x, acc[i][1]+r0.y, acc[i][2]+r0.z, acc[i][3]+r0.w);
        float4 o1 = make_float4(acc[i][4]+r1.x, acc[i][5]+r1.y, acc[i][6]+r1.z, acc[i][7]+r1.w);
        *(float4*)(cp)     = o0;
        *(float4*)(cp + 4) = o1;
    }
}

// ---------------- row softmax over g_S: rows = NB*SEQ, cols = SEQ -----------
__global__ void softmax_rows(float* __restrict__ Sm) {
    __shared__ float sm[8];
    long long row = blockIdx.x;
    float* p = Sm + row * (long long)SEQ;
    int t = threadIdx.x;

    float4 v0 = *(const float4*)(p + t*8);
    float4 v1 = *(const float4*)(p + t*8 + 4);
    float m = fmaxf(fmaxf(fmaxf(v0.x, v0.y), fmaxf(v0.z, v0.w)),
                    fmaxf(fmaxf(v1.x, v1.y), fmaxf(v1.z, v1.w)));
    m = blk_max(m, sm);

    v0.x = expf(v0.x - m); v0.y = expf(v0.y - m); v0.z = expf(v0.z - m); v0.w = expf(v0.w - m);
    v1.x = expf(v1.x - m); v1.y = expf(v1.y - m); v1.z = expf(v1.z - m); v1.w = expf(v1.w - m);
    float s = v0.x + v0.y + v0.z + v0.w + v1.x + v1.y + v1.z + v1.w;
    s = blk_sum(s, sm);
    float inv = 1.0f / s;

    v0.x *= inv; v0.y *= inv; v0.z *= inv; v0.w *= inv;
    v1.x *= inv; v1.y *= inv; v1.z *= inv; v1.w *= inv;
    *(float4*)(p + t*8)     = v0;
    *(float4*)(p + t*8 + 4) = v1;
}

// ---------------- host orchestration ----------------------------------------
extern "C" void kernel_launch(void* const* d_in, const int* in_sizes, int n_in,
                              void* d_out, int out_size) {
    const float* img   = (const float*)d_in[0];
    const float* refp  = (const float*)d_in[1];
    const float* pose  = (const float*)d_in[2];
    const float* gamma = (const float*)d_in[3];
    const float* beta  = (const float*)d_in[4];
    const float* Wq    = (const float*)d_in[5];
    const float* bq    = (const float*)d_in[6];
    const float* Wk    = (const float*)d_in[7];
    const float* bk    = (const float*)d_in[8];
    const float* Wv    = (const float*)d_in[9];
    const float* bv    = (const float*)d_in[10];
    const float* Wo    = (const float*)d_in[11];
    const float* bo    = (const float*)d_in[12];
    float* out = (float*)d_out;

    float *p_imgn, *p_refn, *p_posen, *p_resid, *p_Q, *p_K, *p_V, *p_S, *p_O;
    cudaGetSymbolAddress((void**)&p_imgn,  g_imgn);
    cudaGetSymbolAddress((void**)&p_refn,  g_refn);
    cudaGetSymbolAddress((void**)&p_posen, g_posen);
    cudaGetSymbolAddress((void**)&p_resid, g_resid);
    cudaGetSymbolAddress((void**)&p_Q,     g_Q);
    cudaGetSymbolAddress((void**)&p_K,     g_K);
    cudaGetSymbolAddress((void**)&p_V,     g_V);
    cudaGetSymbolAddress((void**)&p_S,     g_S);
    cudaGetSymbolAddress((void**)&p_O,     g_O);

    // 1) LayerNorm x3 + residual precompute
    ln3_kernel<<<MTOT, 256>>>(img, refp, pose, gamma, beta,
                              p_imgn, p_refn, p_posen, p_resid);

    // 2) Q/K/V projections (NT, +bias)
    dim3 gq(CH/128, MTOT/128, 1);
    gemm_nt<<<gq, 256>>>(p_refn,  Wq, bq, p_Q, MTOT, CH, CH, 1.0f, 0, 0, 0);
    gemm_nt<<<gq, 256>>>(p_posen, Wk, bk, p_K, MTOT, CH, CH, 1.0f, 0, 0, 0);
    gemm_nt<<<gq, 256>>>(p_imgn,  Wv, bv, p_V, MTOT, CH, CH, 1.0f, 0, 0, 0);

    // 3) scores S = (Q K^T) * EMB^-0.5, batched over NB
    dim3 gs(SEQ/128, SEQ/128, NB);
    gemm_nt<<<gs, 256>>>(p_Q, p_K, nullptr, p_S, SEQ, SEQ, CH, 0.03125f,
                         (long long)SEQ*CH, (long long)SEQ*CH, (long long)SEQ*SEQ);

    // 4) softmax rows
    softmax_rows<<<NB*SEQ, 256>>>(p_S);

    // 5) O = P @ V + (img_n + pose_n), batched
    dim3 go(CH/128, SEQ/128, NB);
    gemm_nn<<<go, 256>>>(p_S, p_V, p_resid, p_O, SEQ, CH, SEQ,
                         (long long)SEQ*SEQ, (long long)SEQ*CH,
                         (long long)SEQ*CH,  (long long)SEQ*CH);

    // 6) out = O @ Wo^T + bo  -> straight into d_out
    dim3 gf(ODIM/128, MTOT/128, 1);
    gemm_nt<<<gf, 256>>>(p_O, Wo, bo, out, MTOT, ODIM, CH, 1.0f, 0, 0, 0);
}

// round 3
// speedup vs baseline: 1.9291x; 1.9291x over previous
#include <cuda_runtime.h>
#include <cuda_bf16.h>
#include <cstdint>

#define CH   1024
#define NB   8
#define SEQ  2048
#define MTOT (NB*SEQ)      // 16384
#define ODIM 768

typedef __nv_bfloat16 bf16;

// ---------------- scratch (device globals) ----------------------------------
#define DEVB __device__ __align__(256)
DEVB bf16 g_imgh [MTOT*CH], g_imgl [MTOT*CH];
DEVB bf16 g_refh [MTOT*CH], g_refl [MTOT*CH];
DEVB bf16 g_poseh[MTOT*CH], g_posel[MTOT*CH];
DEVB float g_resid[MTOT*CH];
DEVB bf16 g_Wqh[CH*CH], g_Wql[CH*CH];
DEVB bf16 g_Wkh[CH*CH], g_Wkl[CH*CH];
DEVB bf16 g_Wvh[CH*CH], g_Wvl[CH*CH];
DEVB bf16 g_Woh[ODIM*CH], g_Wol[ODIM*CH];
DEVB bf16 g_Qh[MTOT*CH], g_Ql[MTOT*CH];
DEVB bf16 g_Kh[MTOT*CH], g_Kl[MTOT*CH];
DEVB bf16 g_Vth[MTOT*CH], g_Vtl[MTOT*CH];        // [NB][CH][SEQ] (V transposed)
DEVB float g_S [(size_t)NB*SEQ*SEQ];
DEVB bf16 g_Ph[(size_t)NB*SEQ*SEQ], g_Pl[(size_t)NB*SEQ*SEQ];
DEVB bf16 g_Oh[MTOT*CH], g_Ol[MTOT*CH];

// ---------------- PTX helpers ------------------------------------------------
__device__ __forceinline__ uint32_t smem_u32(const void* p) {
    uint32_t a;
    asm("{ .reg .u64 t; cvta.to.shared.u64 t, %1; cvt.u32.u64 %0, t; }" : "=r"(a) : "l"(p));
    return a;
}
#define CPASYNC16(dst, src) asm volatile("cp.async.cg.shared.global [%0], [%1], 16;" :: "r"(dst), "l"(src))
#define CPCOMMIT() asm volatile("cp.async.commit_group;" ::: "memory")
#define CPWAIT0()  asm volatile("cp.async.wait_group 0;" ::: "memory")

__device__ __forceinline__ uint32_t lds32(uint32_t a) {
    uint32_t v;
    asm volatile("ld.shared.b32 %0, [%1];" : "=r"(v) : "r"(a));
    return v;
}

#define MMA16816(d, a0, a1, a2, a3, b0, b1) \
    asm volatile("mma.sync.aligned.m16n8k16.row.col.f32.bf16.bf16.f32 " \
        "{%0,%1,%2,%3}, {%4,%5,%6,%7}, {%8,%9}, {%0,%1,%2,%3};" \
        : "+f"((d)[0]), "+f"((d)[1]), "+f"((d)[2]), "+f"((d)[3]) \
        : "r"(a0), "r"(a1), "r"(a2), "r"(a3), "r"(b0), "r"(b1))

__device__ __forceinline__ void split2(float v, bf16& h, bf16& l) {
    h = __float2bfloat16(v);
    l = __float2bfloat16(v - __bfloat162float(h));
}
__device__ __forceinline__ uint32_t pack2(bf16 a, bf16 b) {
    return (uint32_t)__bfloat16_as_ushort(a) | ((uint32_t)__bfloat16_as_ushort(b) << 16);
}

// ---------------- smem geometry ----------------------------------------------
// BK=64 bf16, rows padded to 72 bf16 = 144 B (9 x 16B chunks, 36-bank stride)
#define BK      64
#define ROWB    144
#define TILEB   (128*ROWB)           // 18432
#define STAGEB  (4*TILEB)            // 73728 : Ah, Al, Bh, Bl
#define SMEM_SZ (2*STAGEB)           // 147456

// ---------------- mma.sync split-bf16 NT GEMM --------------------------------
// C[M,N] tile(128x128) = alpha * A[M,K] @ B[N,K]^T (+bias[col]) (+addend)
// mode 0: fp32 out; mode 1: hi/lo bf16 out; mode 2: hi/lo bf16 out TRANSPOSED
struct GemmP {
    const bf16 *Ah, *Al, *Bh, *Bl;
    const float *bias, *addend;
    float *Cf; bf16 *Ch, *Cl;
    long long sAz, sBz, sCz, sAddz;
    int K, N, mode, ldT;
    float alpha;
};

__global__ void __launch_bounds__(256, 1) gemm_tc(GemmP p) {
    extern __shared__ char smem[];
    const uint32_t sb = smem_u32(smem);
    const int tid  = threadIdx.x;
    const int lane = tid & 31;
    const int g    = lane >> 2;        // groupID 0..7
    const int t4   = lane & 3;         // thread-in-group 0..3
    const int wm   = (tid >> 5) & 3;   // warp_m 0..3 (32 rows each)
    const int wn   = (tid >> 5) >> 2;  // warp_n 0..1 (64 cols each)
    const long long z = blockIdx.z;
    const bf16* Ah = p.Ah + z * p.sAz;
    const bf16* Al = p.Al + z * p.sAz;
    const bf16* Bh = p.Bh + z * p.sBz;
    const bf16* Bl = p.Bl + z * p.sBz;
    const int rowA = blockIdx.y << 7, colB = blockIdx.x << 7;
    const long long K = p.K;

    // ---- cp.async thread mapping: row = tid/2, 4 x 16B chunks per tile ------
    const int lrow = tid >> 1;
    const int lcb  = (tid & 1) * 4;
    const bf16* gAh = Ah + (long long)(rowA + lrow) * K + lcb * 8;
    const bf16* gAl = Al + (long long)(rowA + lrow) * K + lcb * 8;
    const bf16* gBh = Bh + (long long)(colB + lrow) * K + lcb * 8;
    const bf16* gBl = Bl + (long long)(colB + lrow) * K + lcb * 8;
    const uint32_t sdst = sb + lrow * ROWB + lcb * 16;

#define LOADCHUNK(buf, kb) do { \
    uint32_t _d = sdst + (buf) * STAGEB; \
    _Pragma("unroll") \
    for (int _i = 0; _i < 4; _i++) { \
        CPASYNC16(_d + _i*16,           gAh + (kb) + _i*8); \
        CPASYNC16(_d + _i*16 + TILEB,   gAl + (kb) + _i*8); \
        CPASYNC16(_d + _i*16 + 2*TILEB, gBh + (kb) + _i*8); \
        CPASYNC16(_d + _i*16 + 3*TILEB, gBl + (kb) + _i*8); \
    } \
    CPCOMMIT(); \
} while (0)

    float acc[2][8][4];
#pragma unroll
    for (int i = 0; i < 2; i++)
#pragma unroll
        for (int j = 0; j < 8; j++)
#pragma unroll
            for (int d = 0; d < 4; d++) acc[i][j][d] = 0.f;

    const int nk = p.K / BK;
    LOADCHUNK(0, 0);

    for (int kt = 0; kt < nk; ++kt) {
        const int b = kt & 1;
        CPWAIT0();
        __syncthreads();
        if (kt + 1 < nk) LOADCHUNK(b ^ 1, (kt + 1) * BK);

        const uint32_t base = sb + b * STAGEB;
#pragma unroll
        for (int ks = 0; ks < 4; ks++) {
            const uint32_t kby = ks * 32 + t4 * 4;   // byte offset of k-frag
            uint32_t ah[2][4], al[2][4];
#pragma unroll
            for (int mi = 0; mi < 2; mi++) {
                uint32_t ra = base + (wm * 32 + mi * 16 + g) * ROWB + kby;
                ah[mi][0] = lds32(ra);
                ah[mi][1] = lds32(ra + 8 * ROWB);
                ah[mi][2] = lds32(ra + 16);
                ah[mi][3] = lds32(ra + 8 * ROWB + 16);
                al[mi][0] = lds32(ra + TILEB);
                al[mi][1] = lds32(ra + TILEB + 8 * ROWB);
                al[mi][2] = lds32(ra + TILEB + 16);
                al[mi][3] = lds32(ra + TILEB + 8 * ROWB + 16);
            }
#pragma unroll
            for (int nj = 0; nj < 8; nj++) {
                uint32_t rb = base + 2 * TILEB + (wn * 64 + nj * 8 + g) * ROWB + kby;
                uint32_t bh0 = lds32(rb),        bh1 = lds32(rb + 16);
                uint32_t bl0 = lds32(rb + TILEB), bl1 = lds32(rb + TILEB + 16);
#pragma unroll
                for (int mi = 0; mi < 2; mi++) {
                    MMA16816(acc[mi][nj], ah[mi][0], ah[mi][1], ah[mi][2], ah[mi][3], bh0, bh1);
                    MMA16816(acc[mi][nj], ah[mi][0], ah[mi][1], ah[mi][2], ah[mi][3], bl0, bl1);
                    MMA16816(acc[mi][nj], al[mi][0], al[mi][1], al[mi][2], al[mi][3], bh0, bh1);
                }
            }
        }
    }

    // ---------------- epilogue ----------------------------------------------
    const bool hb = (p.bias   != nullptr);
    const bool ha = (p.addend != nullptr);
    const float* addz = ha ? p.addend + z * p.sAddz : nullptr;
    const float alpha = p.alpha;

    if (p.mode != 2) {
        float* Cf = p.Cf ? p.Cf + z * p.sCz : nullptr;
        bf16* Chp = p.Ch ? p.Ch + z * p.sCz : nullptr;
        bf16* Clp = p.Cl ? p.Cl + z * p.sCz : nullptr;
        const long long N = p.N;
#pragma unroll
        for (int mi = 0; mi < 2; mi++) {
#pragma unroll
            for (int nj = 0; nj < 8; nj++) {
                const int c  = colB + wn * 64 + nj * 8 + t4 * 2;
                const long long r0 = rowA + wm * 32 + mi * 16 + g;
                const long long r1 = r0 + 8;
                float bi0 = hb ? p.bias[c]     : 0.f;
                float bi1 = hb ? p.bias[c + 1] : 0.f;
                float v0 = fmaf(alpha, acc[mi][nj][0], bi0);
                float v1 = fmaf(alpha, acc[mi][nj][1], bi1);
                float v2 = fmaf(alpha, acc[mi][nj][2], bi0);
                float v3 = fmaf(alpha, acc[mi][nj][3], bi1);
                if (ha) {
                    const float2 a0 = *(const float2*)(addz + r0 * N + c);
                    const float2 a1 = *(const float2*)(addz + r1 * N + c);
                    v0 += a0.x; v1 += a0.y; v2 += a1.x; v3 += a1.y;
                }
                if (p.mode == 0) {
                    *(float2*)(Cf + r0 * N + c) = make_float2(v0, v1);
                    *(float2*)(Cf + r1 * N + c) = make_float2(v2, v3);
                } else {
                    bf16 h0, l0, h1, l1, h2, l2, h3, l3;
                    split2(v0, h0, l0); split2(v1, h1, l1);
                    split2(v2, h2, l2); split2(v3, h3, l3);
                    *(uint32_t*)(Chp + r0 * N + c) = pack2(h0, h1);
                    *(uint32_t*)(Chp + r1 * N + c) = pack2(h2, h3);
                    *(uint32_t*)(Clp + r0 * N + c) = pack2(l0, l1);
                    *(uint32_t*)(Clp + r1 * N + c) = pack2(l2, l3);
                }
            }
        }
    } else {
        // transposed hi/lo store: stage full 128x128 fp32 tile in smem
        __syncthreads();                       // all warps done with tiles
        float* st = (float*)smem;              // [128][133]
        bf16* Chp = p.Ch + z * p.sCz;
        bf16* Clp = p.Cl + z * p.sCz;
#pragma unroll
        for (int mi = 0; mi < 2; mi++) {
#pragma unroll
            for (int nj = 0; nj < 8; nj++) {
                const int cl = wn * 64 + nj * 8 + t4 * 2;
                const int r0 = wm * 32 + mi * 16 + g;
                float bi0 = hb ? p.bias[colB + cl]     : 0.f;
                float bi1 = hb ? p.bias[colB + cl + 1] : 0.f;
                st[r0 * 133 + cl]           = fmaf(alpha, acc[mi][nj][0], bi0);
                st[r0 * 133 + cl + 1]       = fmaf(alpha, acc[mi][nj][1], bi1);
                st[(r0 + 8) * 133 + cl]     = fmaf(alpha, acc[mi][nj][2], bi0);
                st[(r0 + 8) * 133 + cl + 1] = fmaf(alpha, acc[mi][nj][3], bi1);
            }
        }
        __syncthreads();
#pragma unroll
        for (int i = 0; i < 64; i++) {
            int idx = tid + i * 256;           // 0..16383
            int cc  = idx >> 7;                // output col 0..127
            int rr  = idx & 127;               // output row 0..127
            float v = st[rr * 133 + cc];
            bf16 h, l; split2(v, h, l);
            long long o = (long long)(colB + cc) * p.ldT + rowA + rr;
            Chp[o] = h; Clp[o] = l;
        }
    }
}

// ---------------- reductions -------------------------------------------------
__device__ __forceinline__ float2 blk_sum2(float a, float b, float2* sm) {
    int lane = threadIdx.x & 31, w = threadIdx.x >> 5;
#pragma unroll
    for (int o = 16; o; o >>= 1) {
        a += __shfl_xor_sync(0xffffffffu, a, o);
        b += __shfl_xor_sync(0xffffffffu, b, o);
    }
    if (lane == 0) sm[w] = make_float2(a, b);
    __syncthreads();
    float sa = 0.f, sb = 0.f;
#pragma unroll
    for (int i = 0; i < 8; i++) { sa += sm[i].x; sb += sm[i].y; }
    __syncthreads();
    return make_float2(sa, sb);
}
__device__ __forceinline__ float blk_max(float a, float* sm) {
    int lane = threadIdx.x & 31, w = threadIdx.x >> 5;
#pragma unroll
    for (int o = 16; o; o >>= 1) a = fmaxf(a, __shfl_xor_sync(0xffffffffu, a, o));
    if (lane == 0) sm[w] = a;
    __syncthreads();
    float m = sm[0];
#pragma unroll
    for (int i = 1; i < 8; i++) m = fmaxf(m, sm[i]);
    __syncthreads();
    return m;
}
__device__ __forceinline__ float blk_sum(float a, float* sm) {
    int lane = threadIdx.x & 31, w = threadIdx.x >> 5;
#pragma unroll
    for (int o = 16; o; o >>= 1) a += __shfl_xor_sync(0xffffffffu, a, o);
    if (lane == 0) sm[w] = a;
    __syncthreads();
    float s = 0.f;
#pragma unroll
    for (int i = 0; i < 8; i++) s += sm[i];
    __syncthreads();
    return s;
}

// ---------------- fused triple LayerNorm -> hi/lo bf16 + fp32 residual ------
__global__ void ln3_kernel(const float* __restrict__ img, const float* __restrict__ refp,
                           const float* __restrict__ pose,
                           const float* __restrict__ gamma, const float* __restrict__ beta,
                           bf16* __restrict__ imgh, bf16* __restrict__ imgl,
                           bf16* __restrict__ refh, bf16* __restrict__ refl,
                           bf16* __restrict__ poseh, bf16* __restrict__ posel,
                           float* __restrict__ resid) {
    __shared__ float2 sm[8];
    long long row  = blockIdx.x;
    int       t    = threadIdx.x;
    long long base = row * CH + (long long)t * 4;

    float4 g  = *(const float4*)(gamma + t * 4);
    float4 be = *(const float4*)(beta  + t * 4);
    float4 keep = make_float4(0.f, 0.f, 0.f, 0.f);

    const float* srcs[3] = {img, refp, pose};
    bf16* dh[3] = {imgh, refh, poseh};
    bf16* dl[3] = {imgl, refl, posel};

#pragma unroll
    for (int s = 0; s < 3; s++) {
        float4 x = *(const float4*)(srcs[s] + base);
        float su = x.x + x.y + x.z + x.w;
        float sq = x.x*x.x + x.y*x.y + x.z*x.z + x.w*x.w;
        float2 rr = blk_sum2(su, sq, sm);
        float mean = rr.x * (1.0f / CH);
        float var  = rr.y * (1.0f / CH) - mean * mean;
        float rstd = rsqrtf(var + 1e-5f);
        float4 y;
        y.x = (x.x - mean) * rstd * g.x + be.x;
        y.y = (x.y - mean) * rstd * g.y + be.y;
        y.z = (x.z - mean) * rstd * g.z + be.z;
        y.w = (x.w - mean) * rstd * g.w + be.w;
        bf16 h0, l0, h1, l1, h2, l2, h3, l3;
        split2(y.x, h0, l0); split2(y.y, h1, l1);
        split2(y.z, h2, l2); split2(y.w, h3, l3);
        *(uint32_t*)(dh[s] + base)     = pack2(h0, h1);
        *(uint32_t*)(dh[s] + base + 2) = pack2(h2, h3);
        *(uint32_t*)(dl[s] + base)     = pack2(l0, l1);
        *(uint32_t*)(dl[s] + base + 2) = pack2(l2, l3);
        if (s == 0) keep = y;
        if (s == 2) {
            float4 rv = make_float4(keep.x + y.x, keep.y + y.y, keep.z + y.z, keep.w + y.w);
            *(float4*)(resid + base) = rv;
        }
    }
}

// ---------------- softmax rows -> hi/lo bf16 ---------------------------------
__global__ void softmax_rows(const float* __restrict__ Sm,
                             bf16* __restrict__ Ph, bf16* __restrict__ Pl) {
    __shared__ float sm[8];
    long long row = blockIdx.x;
    const float* p = Sm + row * (long long)SEQ;
    int t = threadIdx.x;

    float4 v0 = *(const float4*)(p + t * 8);
    float4 v1 = *(const float4*)(p + t * 8 + 4);
    float m = fmaxf(fmaxf(fmaxf(v0.x, v0.y), fmaxf(v0.z, v0.w)),
                    fmaxf(fmaxf(v1.x, v1.y), fmaxf(v1.z, v1.w)));
    m = blk_max(m, sm);

    v0.x = expf(v0.x - m); v0.y = expf(v0.y - m); v0.z = expf(v0.z - m); v0.w = expf(v0.w - m);
    v1.x = expf(v1.x - m); v1.y = expf(v1.y - m); v1.z = expf(v1.z - m); v1.w = expf(v1.w - m);
    float s = v0.x + v0.y + v0.z + v0.w + v1.x + v1.y + v1.z + v1.w;
    s = blk_sum(s, sm);
    float inv = 1.0f / s;

    float vv[8] = {v0.x*inv, v0.y*inv, v0.z*inv, v0.w*inv,
                   v1.x*inv, v1.y*inv, v1.z*inv, v1.w*inv};
    bf16* ph = Ph + row * (long long)SEQ + t * 8;
    bf16* pl = Pl + row * (long long)SEQ + t * 8;
    bf16 h[8], l[8];
#pragma unroll
    for (int i = 0; i < 8; i++) split2(vv[i], h[i], l[i]);
#pragma unroll
    for (int i = 0; i < 4; i++) {
        *(uint32_t*)(ph + i * 2) = pack2(h[i*2], h[i*2+1]);
        *(uint32_t*)(pl + i * 2) = pack2(l[i*2], l[i*2+1]);
    }
}

// ---------------- fp32 -> hi/lo bf16 split (weights) -------------------------
__global__ void split_w(const float* __restrict__ w, bf16* __restrict__ h,
                        bf16* __restrict__ l, int n4) {
    int i = blockIdx.x * blockDim.x + threadIdx.x;
    if (i >= n4) return;
    float4 v = *(const float4*)(w + (long long)i * 4);
    bf16 hh[4], ll[4];
    split2(v.x, hh[0], ll[0]); split2(v.y, hh[1], ll[1]);
    split2(v.z, hh[2], ll[2]); split2(v.w, hh[3], ll[3]);
    *(uint32_t*)(h + (long long)i*4)     = pack2(hh[0], hh[1]);
    *(uint32_t*)(h + (long long)i*4 + 2) = pack2(hh[2], hh[3]);
    *(uint32_t*)(l + (long long)i*4)     = pack2(ll[0], ll[1]);
    *(uint32_t*)(l + (long long)i*4 + 2) = pack2(ll[2], ll[3]);
}

// ---------------- host orchestration ----------------------------------------
extern "C" void kernel_launch(void* const* d_in, const int* in_sizes, int n_in,
                              void* d_out, int out_size) {
    const float* img   = (const float*)d_in[0];
    const float* refp  = (const float*)d_in[1];
    const float* pose  = (const float*)d_in[2];
    const float* gamma = (const float*)d_in[3];
    const float* beta  = (const float*)d_in[4];
    const float* Wq    = (const float*)d_in[5];
    const float* bq    = (const float*)d_in[6];
    const float* Wk    = (const float*)d_in[7];
    const float* bk    = (const float*)d_in[8];
    const float* Wv    = (const float*)d_in[9];
    const float* bv    = (const float*)d_in[10];
    const float* Wo    = (const float*)d_in[11];
    const float* bo    = (const float*)d_in[12];
    float* out = (float*)d_out;

    cudaFuncSetAttribute(gemm_tc, cudaFuncAttributeMaxDynamicSharedMemorySize, SMEM_SZ);

    bf16 *imgh, *imgl, *refh, *refl, *poseh, *posel;
    bf16 *Wqh, *Wql, *Wkh, *Wkl, *Wvh, *Wvl, *Woh, *Wol;
    bf16 *Qh, *Ql, *Kh, *Kl, *Vth, *Vtl, *Phb, *Plb, *Oh, *Ol;
    float *resid, *Sbuf;
    cudaGetSymbolAddress((void**)&imgh, g_imgh);   cudaGetSymbolAddress((void**)&imgl, g_imgl);
    cudaGetSymbolAddress((void**)&refh, g_refh);   cudaGetSymbolAddress((void**)&refl, g_refl);
    cudaGetSymbolAddress((void**)&poseh, g_poseh); cudaGetSymbolAddress((void**)&posel, g_posel);
    cudaGetSymbolAddress((void**)&resid, g_resid);
    cudaGetSymbolAddress((void**)&Wqh, g_Wqh); cudaGetSymbolAddress((void**)&Wql, g_Wql);
    cudaGetSymbolAddress((void**)&Wkh, g_Wkh); cudaGetSymbolAddress((void**)&Wkl, g_Wkl);
    cudaGetSymbolAddress((void**)&Wvh, g_Wvh); cudaGetSymbolAddress((void**)&Wvl, g_Wvl);
    cudaGetSymbolAddress((void**)&Woh, g_Woh); cudaGetSymbolAddress((void**)&Wol, g_Wol);
    cudaGetSymbolAddress((void**)&Qh, g_Qh);   cudaGetSymbolAddress((void**)&Ql, g_Ql);
    cudaGetSymbolAddress((void**)&Kh, g_Kh);   cudaGetSymbolAddress((void**)&Kl, g_Kl);
    cudaGetSymbolAddress((void**)&Vth, g_Vth); cudaGetSymbolAddress((void**)&Vtl, g_Vtl);
    cudaGetSymbolAddress((void**)&Sbuf, g_S);
    cudaGetSymbolAddress((void**)&Phb, g_Ph);  cudaGetSymbolAddress((void**)&Plb, g_Pl);
    cudaGetSymbolAddress((void**)&Oh, g_Oh);   cudaGetSymbolAddress((void**)&Ol, g_Ol);

    // 0) split weights to hi/lo bf16
    split_w<<<(CH*CH/4 + 255)/256, 256>>>(Wq, Wqh, Wql, CH*CH/4);
    split_w<<<(CH*CH/4 + 255)/256, 256>>>(Wk, Wkh, Wkl, CH*CH/4);
    split_w<<<(CH*CH/4 + 255)/256, 256>>>(Wv, Wvh, Wvl, CH*CH/4);
    split_w<<<(ODIM*CH/4 + 255)/256, 256>>>(Wo, Woh, Wol, ODIM*CH/4);

    // 1) LayerNorm x3 -> hi/lo + residual
    ln3_kernel<<<MTOT, 256>>>(img, refp, pose, gamma, beta,
                              imgh, imgl, refh, refl, poseh, posel, resid);

    // 2) Q = refn @ Wq^T + bq   -> hi/lo
    {
        GemmP p{refh, refl, Wqh, Wql, bq, nullptr, nullptr, Qh, Ql,
                0, 0, 0, 0, CH, CH, 1, 0, 1.0f};
        gemm_tc<<<dim3(CH/128, MTOT/128, 1), 256, SMEM_SZ>>>(p);
    }
    // 3) K = posen @ Wk^T + bk  -> hi/lo
    {
        GemmP p{poseh, posel, Wkh, Wkl, bk, nullptr, nullptr, Kh, Kl,
                0, 0, 0, 0, CH, CH, 1, 0, 1.0f};
        gemm_tc<<<dim3(CH/128, MTOT/128, 1), 256, SMEM_SZ>>>(p);
    }
    // 4) V = imgn @ Wv^T + bv   -> hi/lo TRANSPOSED per batch: Vt[b][n][m]
    {
        GemmP p{imgh, imgl, Wvh, Wvl, bv, nullptr, nullptr, Vth, Vtl,
                (long long)SEQ*CH, 0, (long long)CH*SEQ, 0, CH, CH, 2, SEQ, 1.0f};
        gemm_tc<<<dim3(CH/128, SEQ/128, NB), 256, SMEM_SZ>>>(p);
    }
    // 5) S = (Q @ K^T) * EMB^-0.5, batched -> fp32
    {
        GemmP p{Qh, Ql, Kh, Kl, nullptr, nullptr, Sbuf, nullptr, nullptr,
                (long long)SEQ*CH, (long long)SEQ*CH, (long long)SEQ*SEQ, 0,
                CH, SEQ, 0, 0, 0.03125f};
        gemm_tc<<<dim3(SEQ/128, SEQ/128, NB), 256, SMEM_SZ>>>(p);
    }
    // 6) softmax -> hi/lo P
    softmax_rows<<<NB*SEQ, 256>>>(Sbuf, Phb, Plb);
    // 7) O = P @ Vt^T + resid, batched -> hi/lo
    {
        GemmP p{Phb, Plb, Vth, Vtl, nullptr, resid, nullptr, Oh, Ol,
                (long long)SEQ*SEQ, (long long)CH*SEQ, (long long)SEQ*CH, (long long)SEQ*CH,
                SEQ, CH, 1, 0, 1.0f};
        gemm_tc<<<dim3(CH/128, SEQ/128, NB), 256, SMEM_SZ>>>(p);
    }
    // 8) out = O @ Wo^T + bo -> fp32 d_out
    {
        GemmP p{Oh, Ol, Woh, Wol, bo, nullptr, out, nullptr, nullptr,
                0, 0, 0, 0, CH, ODIM, 0, 0, 1.0f};
        gemm_tc<<<dim3(ODIM/128, MTOT/128, 1), 256, SMEM_SZ>>>(p);
    }
}

// round 4
// speedup vs baseline: 1.9876x; 1.0303x over previous
#include <cuda_runtime.h>
#include <cuda_bf16.h>
#include <cstdint>

#define CH   1024
#define NB   8
#define SEQ  2048
#define MTOT (NB*SEQ)      // 16384
#define ODIM 768

typedef __nv_bfloat16 bf16;

// ---------------- scratch (device globals) ----------------------------------
#define DEVB __device__ __align__(256)
DEVB bf16 g_imgh [MTOT*CH], g_imgl [MTOT*CH];
DEVB bf16 g_refh [MTOT*CH], g_refl [MTOT*CH];
DEVB bf16 g_poseh[MTOT*CH], g_posel[MTOT*CH];
DEVB float g_resid[MTOT*CH];
DEVB bf16 g_Wqh[CH*CH], g_Wql[CH*CH];
DEVB bf16 g_Wkh[CH*CH], g_Wkl[CH*CH];
DEVB bf16 g_Wvh[CH*CH], g_Wvl[CH*CH];
DEVB bf16 g_Woh[ODIM*CH], g_Wol[ODIM*CH];
DEVB bf16 g_Qh[MTOT*CH], g_Ql[MTOT*CH];
DEVB bf16 g_Kh[MTOT*CH], g_Kl[MTOT*CH];
DEVB bf16 g_Vth[MTOT*CH], g_Vtl[MTOT*CH];        // [NB][CH][SEQ] (V transposed)
DEVB float g_S [(size_t)NB*SEQ*SEQ];
DEVB bf16 g_Ph[(size_t)NB*SEQ*SEQ], g_Pl[(size_t)NB*SEQ*SEQ];
DEVB bf16 g_Oh[MTOT*CH], g_Ol[MTOT*CH];

// ---------------- PTX helpers ------------------------------------------------
__device__ __forceinline__ uint32_t smem_u32(const void* p) {
    uint32_t a;
    asm("{ .reg .u64 t; cvta.to.shared.u64 t, %1; cvt.u32.u64 %0, t; }" : "=r"(a) : "l"(p));
    return a;
}
#define CPASYNC16(dst, src) asm volatile("cp.async.cg.shared.global [%0], [%1], 16;" :: "r"(dst), "l"(src))
#define CPCOMMIT() asm volatile("cp.async.commit_group;" ::: "memory")
#define CPWAIT0()  asm volatile("cp.async.wait_group 0;" ::: "memory")

#define LDSM4(r0, r1, r2, r3, addr) \
    asm volatile("ldmatrix.sync.aligned.m8n8.x4.shared.b16 {%0,%1,%2,%3}, [%4];" \
        : "=r"(r0), "=r"(r1), "=r"(r2), "=r"(r3) : "r"(addr))

#define MMA16816(d, a0, a1, a2, a3, b0, b1) \
    asm volatile("mma.sync.aligned.m16n8k16.row.col.f32.bf16.bf16.f32 " \
        "{%0,%1,%2,%3}, {%4,%5,%6,%7}, {%8,%9}, {%0,%1,%2,%3};" \
        : "+f"((d)[0]), "+f"((d)[1]), "+f"((d)[2]), "+f"((d)[3]) \
        : "r"(a0), "r"(a1), "r"(a2), "r"(a3), "r"(b0), "r"(b1))

__device__ __forceinline__ void split2(float v, bf16& h, bf16& l) {
    h = __float2bfloat16(v);
    l = __float2bfloat16(v - __bfloat162float(h));
}
__device__ __forceinline__ uint32_t pack2(bf16 a, bf16 b) {
    return (uint32_t)__bfloat16_as_ushort(a) | ((uint32_t)__bfloat16_as_ushort(b) << 16);
}

// ---------------- smem geometry ----------------------------------------------
// BK=64 bf16, rows padded to 72 bf16 = 144 B (9 x 16B chunks, 36-bank stride)
#define BK      64
#define ROWB    144
#define TILEB   (128*ROWB)           // 18432
#define STAGEB  (4*TILEB)            // 73728 : Ah, Al, Bh, Bl
#define SMEM_SZ (2*STAGEB)           // 147456

// ---------------- mma.sync split-bf16 NT GEMM --------------------------------
// C[M,N] tile(128x128) = alpha * A[M,K] @ B[N,K]^T (+bias[col]) (+addend)
// mode 0: fp32 out; mode 1: hi/lo bf16 out; mode 2: hi/lo bf16 out TRANSPOSED
struct GemmP {
    const bf16 *Ah, *Al, *Bh, *Bl;
    const float *bias, *addend;
    float *Cf; bf16 *Ch, *Cl;
    long long sAz, sBz, sCz, sAddz;
    int K, N, mode, ldT;
    float alpha;
};

__global__ void __launch_bounds__(256, 1) gemm_tc(GemmP p) {
    extern __shared__ char smem[];
    const uint32_t sb = smem_u32(smem);
    const int tid  = threadIdx.x;
    const int lane = tid & 31;
    const int g    = lane >> 2;        // groupID 0..7
    const int t4   = lane & 3;         // thread-in-group 0..3
    const int wm   = (tid >> 5) & 3;   // warp_m 0..3 (32 rows each)
    const int wn   = (tid >> 5) >> 2;  // warp_n 0..1 (64 cols each)
    const long long z = blockIdx.z;
    const bf16* Ah = p.Ah + z * p.sAz;
    const bf16* Al = p.Al + z * p.sAz;
    const bf16* Bh = p.Bh + z * p.sBz;
    const bf16* Bl = p.Bl + z * p.sBz;
    const int rowA = blockIdx.y << 7, colB = blockIdx.x << 7;
    const long long K = p.K;

    // ---- cp.async thread mapping: row = tid/2, 4 x 16B chunks per tile ------
    const int lrow = tid >> 1;
    const int lcb  = (tid & 1) * 4;
    const bf16* gAh = Ah + (long long)(rowA + lrow) * K + lcb * 8;
    const bf16* gAl = Al + (long long)(rowA + lrow) * K + lcb * 8;
    const bf16* gBh = Bh + (long long)(colB + lrow) * K + lcb * 8;
    const bf16* gBl = Bl + (long long)(colB + lrow) * K + lcb * 8;
    const uint32_t sdst = sb + lrow * ROWB + lcb * 16;

#define LOADCHUNK(buf, kb) do { \
    uint32_t _d = sdst + (buf) * STAGEB; \
    _Pragma("unroll") \
    for (int _i = 0; _i < 4; _i++) { \
        CPASYNC16(_d + _i*16,           gAh + (kb) + _i*8); \
        CPASYNC16(_d + _i*16 + TILEB,   gAl + (kb) + _i*8); \
        CPASYNC16(_d + _i*16 + 2*TILEB, gBh + (kb) + _i*8); \
        CPASYNC16(_d + _i*16 + 3*TILEB, gBl + (kb) + _i*8); \
    } \
    CPCOMMIT(); \
} while (0)

    // ---- ldmatrix lane mapping ----------------------------------------------
    // A x4: quads -> (m0-7,k0), (m8-15,k0), (m0-7,k+16B), (m8-15,k+16B)
    // B x4: quads -> (nj_even rows,k0), (nj_even,+16B), (nj_odd,k0), (nj_odd,+16B)
    const int q  = lane >> 3;
    const int lr = lane & 7;
    const uint32_t aoff = (uint32_t)((wm * 32 + (q & 1) * 8 + lr) * ROWB + (q >> 1) * 16);
    const uint32_t boff = (uint32_t)((wn * 64 + (q >> 1) * 8 + lr) * ROWB + (q & 1) * 16);

    float acc[2][8][4];
#pragma unroll
    for (int i = 0; i < 2; i++)
#pragma unroll
        for (int j = 0; j < 8; j++)
#pragma unroll
            for (int d = 0; d < 4; d++) acc[i][j][d] = 0.f;

    const int nk = p.K / BK;
    LOADCHUNK(0, 0);

    for (int kt = 0; kt < nk; ++kt) {
        const int b = kt & 1;
        CPWAIT0();
        __syncthreads();
        if (kt + 1 < nk) LOADCHUNK(b ^ 1, (kt + 1) * BK);

        const uint32_t base = sb + b * STAGEB;
#pragma unroll
        for (int ks = 0; ks < 4; ks++) {
            const uint32_t kby = ks * 32;
            uint32_t ah[2][4], al[2][4], bh[8][2], bl[8][2];
#pragma unroll
            for (int mi = 0; mi < 2; mi++) {
                uint32_t ra = base + aoff + mi * (16 * ROWB) + kby;
                LDSM4(ah[mi][0], ah[mi][1], ah[mi][2], ah[mi][3], ra);
                LDSM4(al[mi][0], al[mi][1], al[mi][2], al[mi][3], ra + TILEB);
            }
#pragma unroll
            for (int nj2 = 0; nj2 < 4; nj2++) {
                uint32_t rb = base + 2 * TILEB + boff + nj2 * (16 * ROWB) + kby;
                LDSM4(bh[nj2*2][0], bh[nj2*2][1], bh[nj2*2+1][0], bh[nj2*2+1][1], rb);
                LDSM4(bl[nj2*2][0], bl[nj2*2][1], bl[nj2*2+1][0], bl[nj2*2+1][1], rb + TILEB);
            }
            // term 1: hi x hi  (16 independent MMAs)
#pragma unroll
            for (int nj = 0; nj < 8; nj++)
#pragma unroll
                for (int mi = 0; mi < 2; mi++)
                    MMA16816(acc[mi][nj], ah[mi][0], ah[mi][1], ah[mi][2], ah[mi][3],
                             bh[nj][0], bh[nj][1]);
            // term 2: hi x lo
#pragma unroll
            for (int nj = 0; nj < 8; nj++)
#pragma unroll
                for (int mi = 0; mi < 2; mi++)
                    MMA16816(acc[mi][nj], ah[mi][0], ah[mi][1], ah[mi][2], ah[mi][3],
                             bl[nj][0], bl[nj][1]);
            // term 3: lo x hi
#pragma unroll
            for (int nj = 0; nj < 8; nj++)
#pragma unroll
                for (int mi = 0; mi < 2; mi++)
                    MMA16816(acc[mi][nj], al[mi][0], al[mi][1], al[mi][2], al[mi][3],
                             bh[nj][0], bh[nj][1]);
        }
    }

    // ---------------- epilogue ----------------------------------------------
    const bool hb = (p.bias   != nullptr);
    const bool ha = (p.addend != nullptr);
    const float* addz = ha ? p.addend + z * p.sAddz : nullptr;
    const float alpha = p.alpha;

    if (p.mode != 2) {
        float* Cf = p.Cf ? p.Cf + z * p.sCz : nullptr;
        bf16* Chp = p.Ch ? p.Ch + z * p.sCz : nullptr;
        bf16* Clp = p.Cl ? p.Cl + z * p.sCz : nullptr;
        const long long N = p.N;
#pragma unroll
        for (int mi = 0; mi < 2; mi++) {
#pragma unroll
            for (int nj = 0; nj < 8; nj++) {
                const int c  = colB + wn * 64 + nj * 8 + t4 * 2;
                const long long r0 = rowA + wm * 32 + mi * 16 + g;
                const long long r1 = r0 + 8;
                float bi0 = hb ? p.bias[c]     : 0.f;
                float bi1 = hb ? p.bias[c + 1] : 0.f;
                float v0 = fmaf(alpha, acc[mi][nj][0], bi0);
                float v1 = fmaf(alpha, acc[mi][nj][1], bi1);
                float v2 = fmaf(alpha, acc[mi][nj][2], bi0);
                float v3 = fmaf(alpha, acc[mi][nj][3], bi1);
                if (ha) {
                    const float2 a0 = *(const float2*)(addz + r0 * N + c);
                    const float2 a1 = *(const float2*)(addz + r1 * N + c);
                    v0 += a0.x; v1 += a0.y; v2 += a1.x; v3 += a1.y;
                }
                if (p.mode == 0) {
                    *(float2*)(Cf + r0 * N + c) = make_float2(v0, v1);
                    *(float2*)(Cf + r1 * N + c) = make_float2(v2, v3);
                } else {
                    bf16 h0, l0, h1, l1, h2, l2, h3, l3;
                    split2(v0, h0, l0); split2(v1, h1, l1);
                    split2(v2, h2, l2); split2(v3, h3, l3);
                    *(uint32_t*)(Chp + r0 * N + c) = pack2(h0, h1);
                    *(uint32_t*)(Chp + r1 * N + c) = pack2(h2, h3);
                    *(uint32_t*)(Clp + r0 * N + c) = pack2(l0, l1);
                    *(uint32_t*)(Clp + r1 * N + c) = pack2(l2, l3);
                }
            }
        }
    } else {
        // transposed hi/lo store: stage full 128x128 fp32 tile in smem
        __syncthreads();                       // all warps done with tiles
        float* st = (float*)smem;              // [128][133]
        bf16* Chp = p.Ch + z * p.sCz;
        bf16* Clp = p.Cl + z * p.sCz;
#pragma unroll
        for (int mi = 0; mi < 2; mi++) {
#pragma unroll
            for (int nj = 0; nj < 8; nj++) {
                const int cl = wn * 64 + nj * 8 + t4 * 2;
                const int r0 = wm * 32 + mi * 16 + g;
                float bi0 = hb ? p.bias[colB + cl]     : 0.f;
                float bi1 = hb ? p.bias[colB + cl + 1] : 0.f;
                st[r0 * 133 + cl]           = fmaf(alpha, acc[mi][nj][0], bi0);
                st[r0 * 133 + cl + 1]       = fmaf(alpha, acc[mi][nj][1], bi1);
                st[(r0 + 8) * 133 + cl]     = fmaf(alpha, acc[mi][nj][2], bi0);
                st[(r0 + 8) * 133 + cl + 1] = fmaf(alpha, acc[mi][nj][3], bi1);
            }
        }
        __syncthreads();
#pragma unroll
        for (int i = 0; i < 64; i++) {
            int idx = tid + i * 256;           // 0..16383
            int cc  = idx >> 7;                // output col 0..127
            int rr  = idx & 127;               // output row 0..127
            float v = st[rr * 133 + cc];
            bf16 h, l; split2(v, h, l);
            long long o = (long long)(colB + cc) * p.ldT + rowA + rr;
            Chp[o] = h; Clp[o] = l;
        }
    }
}

// ---------------- reductions -------------------------------------------------
__device__ __forceinline__ float2 blk_sum2(float a, float b, float2* sm) {
    int lane = threadIdx.x & 31, w = threadIdx.x >> 5;
#pragma unroll
    for (int o = 16; o; o >>= 1) {
        a += __shfl_xor_sync(0xffffffffu, a, o);
        b += __shfl_xor_sync(0xffffffffu, b, o);
    }
    if (lane == 0) sm[w] = make_float2(a, b);
    __syncthreads();
    float sa = 0.f, sb = 0.f;
#pragma unroll
    for (int i = 0; i < 8; i++) { sa += sm[i].x; sb += sm[i].y; }
    __syncthreads();
    return make_float2(sa, sb);
}
__device__ __forceinline__ float blk_max(float a, float* sm) {
    int lane = threadIdx.x & 31, w = threadIdx.x >> 5;
#pragma unroll
    for (int o = 16; o; o >>= 1) a = fmaxf(a, __shfl_xor_sync(0xffffffffu, a, o));
    if (lane == 0) sm[w] = a;
    __syncthreads();
    float m = sm[0];
#pragma unroll
    for (int i = 1; i < 8; i++) m = fmaxf(m, sm[i]);
    __syncthreads();
    return m;
}
__device__ __forceinline__ float blk_sum(float a, float* sm) {
    int lane = threadIdx.x & 31, w = threadIdx.x >> 5;
#pragma unroll
    for (int o = 16; o; o >>= 1) a += __shfl_xor_sync(0xffffffffu, a, o);
    if (lane == 0) sm[w] = a;
    __syncthreads();
    float s = 0.f;
#pragma unroll
    for (int i = 0; i < 8; i++) s += sm[i];
    __syncthreads();
    return s;
}

// ---------------- fused triple LayerNorm -> hi/lo bf16 + fp32 residual ------
__global__ void ln3_kernel(const float* __restrict__ img, const float* __restrict__ refp,
                           const float* __restrict__ pose,
                           const float* __restrict__ gamma, const float* __restrict__ beta,
                           bf16* __restrict__ imgh, bf16* __restrict__ imgl,
                           bf16* __restrict__ refh, bf16* __restrict__ refl,
                           bf16* __restrict__ poseh, bf16* __restrict__ posel,
                           float* __restrict__ resid) {
    __shared__ float2 sm[8];
    long long row  = blockIdx.x;
    int       t    = threadIdx.x;
    long long base = row * CH + (long long)t * 4;

    float4 g  = *(const float4*)(gamma + t * 4);
    float4 be = *(const float4*)(beta  + t * 4);
    float4 keep = make_float4(0.f, 0.f, 0.f, 0.f);

    const float* srcs[3] = {img, refp, pose};
    bf16* dh[3] = {imgh, refh, poseh};
    bf16* dl[3] = {imgl, refl, posel};

#pragma unroll
    for (int s = 0; s < 3; s++) {
        float4 x = *(const float4*)(srcs[s] + base);
        float su = x.x + x.y + x.z + x.w;
        float sq = x.x*x.x + x.y*x.y + x.z*x.z + x.w*x.w;
        float2 rr = blk_sum2(su, sq, sm);
        float mean = rr.x * (1.0f / CH);
        float var  = rr.y * (1.0f / CH) - mean * mean;
        float rstd = rsqrtf(var + 1e-5f);
        float4 y;
        y.x = (x.x - mean) * rstd * g.x + be.x;
        y.y = (x.y - mean) * rstd * g.y + be.y;
        y.z = (x.z - mean) * rstd * g.z + be.z;
        y.w = (x.w - mean) * rstd * g.w + be.w;
        bf16 h0, l0, h1, l1, h2, l2, h3, l3;
        split2(y.x, h0, l0); split2(y.y, h1, l1);
        split2(y.z, h2, l2); split2(y.w, h3, l3);
        *(uint32_t*)(dh[s] + base)     = pack2(h0, h1);
        *(uint32_t*)(dh[s] + base + 2) = pack2(h2, h3);
        *(uint32_t*)(dl[s] + base)     = pack2(l0, l1);
        *(uint32_t*)(dl[s] + base + 2) = pack2(l2, l3);
        if (s == 0) keep = y;
        if (s == 2) {
            float4 rv = make_float4(keep.x + y.x, keep.y + y.y, keep.z + y.z, keep.w + y.w);
            *(float4*)(resid + base) = rv;
        }
    }
}

// ---------------- softmax rows -> hi/lo bf16 ---------------------------------
__global__ void softmax_rows(const float* __restrict__ Sm,
                             bf16* __restrict__ Ph, bf16* __restrict__ Pl) {
    __shared__ float sm[8];
    long long row = blockIdx.x;
    const float* p = Sm + row * (long long)SEQ;
    int t = threadIdx.x;

    float4 v0 = *(const float4*)(p + t * 8);
    float4 v1 = *(const float4*)(p + t * 8 + 4);
    float m = fmaxf(fmaxf(fmaxf(v0.x, v0.y), fmaxf(v0.z, v0.w)),
                    fmaxf(fmaxf(v1.x, v1.y), fmaxf(v1.z, v1.w)));
    m = blk_max(m, sm);

    v0.x = expf(v0.x - m); v0.y = expf(v0.y - m); v0.z = expf(v0.z - m); v0.w = expf(v0.w - m);
    v1.x = expf(v1.x - m); v1.y = expf(v1.y - m); v1.z = expf(v1.z - m); v1.w = expf(v1.w - m);
    float s = v0.x + v0.y + v0.z + v0.w + v1.x + v1.y + v1.z + v1.w;
    s = blk_sum(s, sm);
    float inv = 1.0f / s;

    float vv[8] = {v0.x*inv, v0.y*inv, v0.z*inv, v0.w*inv,
                   v1.x*inv, v1.y*inv, v1.z*inv, v1.w*inv};
    bf16* ph = Ph + row * (long long)SEQ + t * 8;
    bf16* pl = Pl + row * (long long)SEQ + t * 8;
    bf16 h[8], l[8];
#pragma unroll
    for (int i = 0; i < 8; i++) split2(vv[i], h[i], l[i]);
#pragma unroll
    for (int i = 0; i < 4; i++) {
        *(uint32_t*)(ph + i * 2) = pack2(h[i*2], h[i*2+1]);
        *(uint32_t*)(pl + i * 2) = pack2(l[i*2], l[i*2+1]);
    }
}

// ---------------- fp32 -> hi/lo bf16 split (weights) -------------------------
__global__ void split_w(const float* __restrict__ w, bf16* __restrict__ h,
                        bf16* __restrict__ l, int n4) {
    int i = blockIdx.x * blockDim.x + threadIdx.x;
    if (i >= n4) return;
    float4 v = *(const float4*)(w + (long long)i * 4);
    bf16 hh[4], ll[4];
    split2(v.x, hh[0], ll[0]); split2(v.y, hh[1], ll[1]);
    split2(v.z, hh[2], ll[2]); split2(v.w, hh[3], ll[3]);
    *(uint32_t*)(h + (long long)i*4)     = pack2(hh[0], hh[1]);
    *(uint32_t*)(h + (long long)i*4 + 2) = pack2(hh[2], hh[3]);
    *(uint32_t*)(l + (long long)i*4)     = pack2(ll[0], ll[1]);
    *(uint32_t*)(l + (long long)i*4 + 2) = pack2(ll[2], ll[3]);
}

// ---------------- host orchestration ----------------------------------------
extern "C" void kernel_launch(void* const* d_in, const int* in_sizes, int n_in,
                              void* d_out, int out_size) {
    const float* img   = (const float*)d_in[0];
    const float* refp  = (const float*)d_in[1];
    const float* pose  = (const float*)d_in[2];
    const float* gamma = (const float*)d_in[3];
    const float* beta  = (const float*)d_in[4];
    const float* Wq    = (const float*)d_in[5];
    const float* bq    = (const float*)d_in[6];
    const float* Wk    = (const float*)d_in[7];
    const float* bk    = (const float*)d_in[8];
    const float* Wv    = (const float*)d_in[9];
    const float* bv    = (const float*)d_in[10];
    const float* Wo    = (const float*)d_in[11];
    const float* bo    = (const float*)d_in[12];
    float* out = (float*)d_out;

    cudaFuncSetAttribute(gemm_tc, cudaFuncAttributeMaxDynamicSharedMemorySize, SMEM_SZ);

    bf16 *imgh, *imgl, *refh, *refl, *poseh, *posel;
    bf16 *Wqh, *Wql, *Wkh, *Wkl, *Wvh, *Wvl, *Woh, *Wol;
    bf16 *Qh, *Ql, *Kh, *Kl, *Vth, *Vtl, *Phb, *Plb, *Oh, *Ol;
    float *resid, *Sbuf;
    cudaGetSymbolAddress((void**)&imgh, g_imgh);   cudaGetSymbolAddress((void**)&imgl, g_imgl);
    cudaGetSymbolAddress((void**)&refh, g_refh);   cudaGetSymbolAddress((void**)&refl, g_refl);
    cudaGetSymbolAddress((void**)&poseh, g_poseh); cudaGetSymbolAddress((void**)&posel, g_posel);
    cudaGetSymbolAddress((void**)&resid, g_resid);
    cudaGetSymbolAddress((void**)&Wqh, g_Wqh); cudaGetSymbolAddress((void**)&Wql, g_Wql);
    cudaGetSymbolAddress((void**)&Wkh, g_Wkh); cudaGetSymbolAddress((void**)&Wkl, g_Wkl);
    cudaGetSymbolAddress((void**)&Wvh, g_Wvh); cudaGetSymbolAddress((void**)&Wvl, g_Wvl);
    cudaGetSymbolAddress((void**)&Woh, g_Woh); cudaGetSymbolAddress((void**)&Wol, g_Wol);
    cudaGetSymbolAddress((void**)&Qh, g_Qh);   cudaGetSymbolAddress((void**)&Ql, g_Ql);
    cudaGetSymbolAddress((void**)&Kh, g_Kh);   cudaGetSymbolAddress((void**)&Kl, g_Kl);
    cudaGetSymbolAddress((void**)&Vth, g_Vth); cudaGetSymbolAddress((void**)&Vtl, g_Vtl);
    cudaGetSymbolAddress((void**)&Sbuf, g_S);
    cudaGetSymbolAddress((void**)&Phb, g_Ph);  cudaGetSymbolAddress((void**)&Plb, g_Pl);
    cudaGetSymbolAddress((void**)&Oh, g_Oh);   cudaGetSymbolAddress((void**)&Ol, g_Ol);

    // 0) split weights to hi/lo bf16
    split_w<<<(CH*CH/4 + 255)/256, 256>>>(Wq, Wqh, Wql, CH*CH/4);
    split_w<<<(CH*CH/4 + 255)/256, 256>>>(Wk, Wkh, Wkl, CH*CH/4);
    split_w<<<(CH*CH/4 + 255)/256, 256>>>(Wv, Wvh, Wvl, CH*CH/4);
    split_w<<<(ODIM*CH/4 + 255)/256, 256>>>(Wo, Woh, Wol, ODIM*CH/4);

    // 1) LayerNorm x3 -> hi/lo + residual
    ln3_kernel<<<MTOT, 256>>>(img, refp, pose, gamma, beta,
                              imgh, imgl, refh, refl, poseh, posel, resid);

    // 2) Q = refn @ Wq^T + bq   -> hi/lo
    {
        GemmP p{refh, refl, Wqh, Wql, bq, nullptr, nullptr, Qh, Ql,
                0, 0, 0, 0, CH, CH, 1, 0, 1.0f};
        gemm_tc<<<dim3(CH/128, MTOT/128, 1), 256, SMEM_SZ>>>(p);
    }
    // 3) K = posen @ Wk^T + bk  -> hi/lo
    {
        GemmP p{poseh, posel, Wkh, Wkl, bk, nullptr, nullptr, Kh, Kl,
                0, 0, 0, 0, CH, CH, 1, 0, 1.0f};
        gemm_tc<<<dim3(CH/128, MTOT/128, 1), 256, SMEM_SZ>>>(p);
    }
    // 4) V = imgn @ Wv^T + bv   -> hi/lo TRANSPOSED per batch: Vt[b][n][m]
    {
        GemmP p{imgh, imgl, Wvh, Wvl, bv, nullptr, nullptr, Vth, Vtl,
                (long long)SEQ*CH, 0, (long long)CH*SEQ, 0, CH, CH, 2, SEQ, 1.0f};
        gemm_tc<<<dim3(CH/128, SEQ/128, NB), 256, SMEM_SZ>>>(p);
    }
    // 5) S = (Q @ K^T) * EMB^-0.5, batched -> fp32
    {
        GemmP p{Qh, Ql, Kh, Kl, nullptr, nullptr, Sbuf, nullptr, nullptr,
                (long long)SEQ*CH, (long long)SEQ*CH, (long long)SEQ*SEQ, 0,
                CH, SEQ, 0, 0, 0.03125f};
        gemm_tc<<<dim3(SEQ/128, SEQ/128, NB), 256, SMEM_SZ>>>(p);
    }
    // 6) softmax -> hi/lo P
    softmax_rows<<<NB*SEQ, 256>>>(Sbuf, Phb, Plb);
    // 7) O = P @ Vt^T + resid, batched -> hi/lo
    {
        GemmP p{Phb, Plb, Vth, Vtl, nullptr, resid, nullptr, Oh, Ol,
                (long long)SEQ*SEQ, (long long)CH*SEQ, (long long)SEQ*CH, (long long)SEQ*CH,
                SEQ, CH, 1, 0, 1.0f};
        gemm_tc<<<dim3(CH/128, SEQ/128, NB), 256, SMEM_SZ>>>(p);
    }
    // 8) out = O @ Wo^T + bo -> fp32 d_out
    {
        GemmP p{Oh, Ol, Woh, Wol, bo, nullptr, out, nullptr, nullptr,
                0, 0, 0, 0, CH, ODIM, 0, 0, 1.0f};
        gemm_tc<<<dim3(ODIM/128, MTOT/128, 1), 256, SMEM_SZ>>>(p);
    }
}